// round 4
// baseline (speedup 1.0000x reference)
#include <cuda_runtime.h>
#include <math.h>

#define E_TOT  800000
#define HALF_E 400000
#define TPB    256

// material id per element (0 -> (lam=1.0, mu=0.5), 1 -> (lam=2.0, mu=1.0))
__device__ unsigned char g_matid[E_TOT];

// blocks0 ∪ blocks1 covers every element, so scattering both fully
// initializes g_matid each call — no memset needed. 4x ILP per thread.
__global__ void mark_both_kernel(const int* __restrict__ b0,
                                 const int* __restrict__ b1) {
    int i = blockIdx.x * blockDim.x + threadIdx.x;
    if (i < HALF_E / 4) {
        int4 a = reinterpret_cast<const int4*>(b0)[i];
        int4 b = reinterpret_cast<const int4*>(b1)[i];
        g_matid[a.x] = 0; g_matid[a.y] = 0; g_matid[a.z] = 0; g_matid[a.w] = 0;
        g_matid[b.x] = 1; g_matid[b.y] = 1; g_matid[b.z] = 1; g_matid[b.w] = 1;
    }
}

__global__ void __launch_bounds__(TPB)
hess_kernel(const float* __restrict__ U,        // [N,2]
            const float* __restrict__ state,    // [E,1,1]
            const int*   __restrict__ conns,    // [E,3]
            const float* __restrict__ sg,       // [E,1,3,2]
            const float* __restrict__ vols,     // [E,1]
            float*       __restrict__ out)      // [E,3,2,3,2]
{
    // 18KB buffer: first staged inputs (9KB used), then two output half-passes.
    __shared__ float smem[TPB * 18];

    const int tid = threadIdx.x;
    const int blk = blockIdx.x;
    const int e   = blk * TPB + tid;          // grid exact: 3125*256 = 800000

    // ---- cooperative coalesced staging of sg [6 f/elem] and conns [3 i/elem]
    {
        const float* sgb = sg + (size_t)blk * (TPB * 6);
#pragma unroll
        for (int it = 0; it < 6; it++)
            smem[it * TPB + tid] = sgb[it * TPB + tid];
        int* conn_s = reinterpret_cast<int*>(smem + 6 * TPB);
        const int* cb = conns + (size_t)blk * (TPB * 3);
#pragma unroll
        for (int it = 0; it < 3; it++)
            conn_s[it * TPB + tid] = cb[it * TPB + tid];
    }
    __syncthreads();

    float2 g0, g1, g2;
    {
        const float2* p = reinterpret_cast<const float2*>(smem + tid * 6);
        g0 = p[0]; g1 = p[1]; g2 = p[2];
    }
    int c0, c1, c2;
    {
        const int* conn_s = reinterpret_cast<const int*>(smem + 6 * TPB);
        c0 = conn_s[tid * 3 + 0];
        c1 = conn_s[tid * 3 + 1];
        c2 = conn_s[tid * 3 + 2];
    }

    float vol = __ldg(&vols[e]);
    float Q   = __ldg(&state[e]);
    int   m   = g_matid[e];

    float lam = m ? 2.0f : 1.0f;
    float mu  = m ? 1.0f : 0.5f;
    float mu_eff = mu * (1.0f + 0.01f * Q);

    // ---- gather nodal displacements (L2-resident table) ----
    const float2* U2 = reinterpret_cast<const float2*>(U);
    float2 u0 = __ldg(&U2[c0]);
    float2 u1 = __ldg(&U2[c1]);
    float2 u2 = __ldg(&U2[c2]);

    __syncthreads();   // staged inputs consumed; buffer reusable

    // gradU[c][d] = sum_n U[n][c] * g[n][d]
    float G00 = u0.x * g0.x + u1.x * g1.x + u2.x * g2.x;
    float G01 = u0.x * g0.y + u1.x * g1.y + u2.x * g2.y;
    float G10 = u0.y * g0.x + u1.y * g1.x + u2.y * g2.x;
    float G11 = u0.y * g0.y + u1.y * g1.y + u2.y * g2.y;

    float F00 = 1.0f + G00, F01 = G01;
    float F10 = G10,        F11 = 1.0f + G11;

    float J    = F00 * F11 - F01 * F10;
    float logJ = __logf(J);
    float invJ = __frcp_rn(J);

    float i00 =  F11 * invJ, i01 = -F01 * invJ;
    float i10 = -F10 * invJ, i11 =  F00 * invJ;

    float ga[3][2] = { {g0.x, g0.y}, {g1.x, g1.y}, {g2.x, g2.y} };

    float h[3][2];
#pragma unroll
    for (int a = 0; a < 3; a++) {
        h[a][0] = ga[a][0] * i00 + ga[a][1] * i10;
        h[a][1] = ga[a][0] * i01 + ga[a][1] * i11;
    }

    float cgeo = mu_eff - lam * logJ;

    // H[a,i,b,j] = vol*( mu_eff*delta_ij*(g_a . g_b)
    //                    + cgeo * h_a[j]*h_b[i] + lam * h_a[i]*h_b[j] )
    float o[36];
#pragma unroll
    for (int a = 0; a < 3; a++) {
#pragma unroll
        for (int b = 0; b < 3; b++) {
            float gg = ga[a][0] * ga[b][0] + ga[a][1] * ga[b][1];
#pragma unroll
            for (int i = 0; i < 2; i++) {
#pragma unroll
                for (int j = 0; j < 2; j++) {
                    float v = cgeo * h[a][j] * h[b][i] + lam * h[a][i] * h[b][j];
                    if (i == j) v += mu_eff * gg;
                    o[((a * 2 + i) * 3 + b) * 2 + j] = v * vol;
                }
            }
        }
    }

    // ---- two half-passes: stage 18 floats/elem (stride 18, STS.64
    // conflict-free: banks 18t mod 32 distinct per 16-lane phase), then
    // linear coalesced copy-out of 18KB.
    float4* o4base = reinterpret_cast<float4*>(out) + (size_t)blk * (TPB * 9);
#pragma unroll
    for (int half = 0; half < 2; half++) {
        float2* row = reinterpret_cast<float2*>(smem + tid * 18);
#pragma unroll
        for (int k = 0; k < 9; k++) {
            int s = half * 18 + 2 * k;
            row[k] = make_float2(o[s], o[s + 1]);
        }
        __syncthreads();
        // this half of the output region: float4 index j in [half*1152*2 ... )
        // per half: TPB*18 floats = TPB*4.5 float4 = 1152 float4
        const float4* s4 = reinterpret_cast<const float4*>(smem);
#pragma unroll
        for (int it = 0; it < 5; it++) {
            int j = it * TPB + tid;
            if (j < (TPB * 18) / 4) {
                // global float4 index within block's output for this half:
                // element el = j/ (18/4)... simpler: half h covers bytes
                // [h*72 .. h*72+72) of each element, but we staged
                // element-contiguous half-rows, so the smem buffer maps to
                // out interleaved. Reconstruct: smem float index f = 4j,
                // el = f/18, k = f%18, out float index = el*36 + half*18 + k.
                int f  = 4 * j;
                int el = f / 18;
                int k  = f - el * 18;
                float4 v = s4[j];
                // k is 0,4,8,12,16,2,6,10,14 pattern mod 18 — always even,
                // and 4j is 16B aligned in smem; out offset el*36+half*18+k:
                // el*36*4B is 16B-multiple? 36 floats=144B yes; half*18+k even
                // but k=16 -> crosses? k+4 <= 18 requires k<=14; k=16 would
                // straddle. 4j mod 18: j=4 -> f=16, el=0,k=16 -> straddles
                // element boundary! handle with scalar fallback for k==16/14?
                if (k <= 14) {
                    float* op = out + (size_t)blk * (TPB * 36) + (size_t)el * 36 + half * 18 + k;
                    op[0] = v.x; op[1] = v.y; op[2] = v.z; op[3] = v.w;
                } else { // k == 16: last 2 floats of el, first 2 of el+1
                    float* op0 = out + (size_t)blk * (TPB * 36) + (size_t)el * 36 + half * 18 + 16;
                    op0[0] = v.x; op0[1] = v.y;
                    float* op1 = out + (size_t)blk * (TPB * 36) + (size_t)(el + 1) * 36 + half * 18;
                    op1[0] = v.z; op1[1] = v.w;
                }
            }
        }
        __syncthreads();
    }
    (void)o4base;
}

extern "C" void kernel_launch(void* const* d_in, const int* in_sizes, int n_in,
                              void* d_out, int out_size) {
    // metadata order: U, coords, state, conns, shapes, shapeGrads, vols, blocks0, blocks1
    const float* U      = (const float*)d_in[0];
    const float* state  = (const float*)d_in[2];
    const int*   conns  = (const int*)  d_in[3];
    const float* sg     = (const float*)d_in[5];
    const float* vols   = (const float*)d_in[6];
    const int*   b0     = (const int*)  d_in[7];
    const int*   b1     = (const int*)  d_in[8];
    float* out = (float*)d_out;

    mark_both_kernel<<<(HALF_E / 4 + TPB - 1) / TPB, TPB>>>(b0, b1);

    hess_kernel<<<E_TOT / TPB, TPB>>>(U, state, conns, sg, vols, out);
}

// round 5
// speedup vs baseline: 2.6830x; 2.6830x over previous
#include <cuda_runtime.h>
#include <math.h>

#define E_TOT  800000
#define HALF_E 400000
#define TPB    256

// material id per element (0 -> (lam=1.0, mu=0.5), 1 -> (lam=2.0, mu=1.0))
__device__ unsigned char g_matid[E_TOT];

// scatter ones for block1 only (zeroing via cudaMemsetAsync); 4x ILP
__global__ void mark_b1_kernel(const int* __restrict__ b1) {
    int i = blockIdx.x * blockDim.x + threadIdx.x;
    if (i < HALF_E / 4) {
        int4 b = reinterpret_cast<const int4*>(b1)[i];
        g_matid[b.x] = 1;
        g_matid[b.y] = 1;
        g_matid[b.z] = 1;
        g_matid[b.w] = 1;
    }
}

__global__ void __launch_bounds__(TPB)
hess_kernel(const float* __restrict__ U,        // [N,2]
            const float* __restrict__ state,    // [E,1,1]
            const int*   __restrict__ conns,    // [E,3]
            const float* __restrict__ sg,       // [E,1,3,2]
            const float* __restrict__ vols,     // [E,1]
            float*       __restrict__ out)      // [E,3,2,3,2]
{
    // Buffer reused: staged sg inputs first, then staged outputs
    // (element-contiguous, stride 36 floats = 144B, 16B aligned).
    __shared__ float smem[TPB * 36];

    const int tid = threadIdx.x;
    const int blk = blockIdx.x;
    const int e   = blk * TPB + tid;          // grid exact: 3125*256 = 800000

    // ---- issue the random U gathers FIRST (longest latency path):
    // direct conns load (no smem roundtrip) -> immediate dependent gather.
    int c0 = __ldg(&conns[3 * e + 0]);
    int c1 = __ldg(&conns[3 * e + 1]);
    int c2 = __ldg(&conns[3 * e + 2]);

    const float2* U2 = reinterpret_cast<const float2*>(U);
    float2 u0 = __ldg(&U2[c0]);
    float2 u1 = __ldg(&U2[c1]);
    float2 u2 = __ldg(&U2[c2]);

    float vol = __ldg(&vols[e]);
    float Q   = __ldg(&state[e]);
    int   m   = g_matid[e];

    // ---- cooperative coalesced staging of sg [6 floats/elem], overlaps
    // with the in-flight gathers above.
    {
        const float* sgb = sg + (size_t)blk * (TPB * 6);
#pragma unroll
        for (int it = 0; it < 6; it++)
            smem[it * TPB + tid] = sgb[it * TPB + tid];
    }
    __syncthreads();

    float2 g0, g1, g2;
    {
        const float2* p = reinterpret_cast<const float2*>(smem + tid * 6);
        g0 = p[0]; g1 = p[1]; g2 = p[2];
    }
    __syncthreads();   // staged inputs consumed; buffer reusable for output

    float lam = m ? 2.0f : 1.0f;
    float mu  = m ? 1.0f : 0.5f;
    float mu_eff = mu * (1.0f + 0.01f * Q);

    // gradU[c][d] = sum_n U[n][c] * g[n][d]
    float G00 = u0.x * g0.x + u1.x * g1.x + u2.x * g2.x;
    float G01 = u0.x * g0.y + u1.x * g1.y + u2.x * g2.y;
    float G10 = u0.y * g0.x + u1.y * g1.x + u2.y * g2.x;
    float G11 = u0.y * g0.y + u1.y * g1.y + u2.y * g2.y;

    float F00 = 1.0f + G00, F01 = G01;
    float F10 = G10,        F11 = 1.0f + G11;

    float J    = F00 * F11 - F01 * F10;
    float logJ = __logf(J);
    float invJ = __frcp_rn(J);

    // Finv[l][i]
    float i00 =  F11 * invJ, i01 = -F01 * invJ;
    float i10 = -F10 * invJ, i11 =  F00 * invJ;

    float ga[3][2] = { {g0.x, g0.y}, {g1.x, g1.y}, {g2.x, g2.y} };

    // h[a][i] = sum_l g_a[l] * Finv[l][i]
    float h[3][2];
#pragma unroll
    for (int a = 0; a < 3; a++) {
        h[a][0] = ga[a][0] * i00 + ga[a][1] * i10;
        h[a][1] = ga[a][0] * i01 + ga[a][1] * i11;
    }

    float cgeo = mu_eff - lam * logJ;

    // H[a,i,b,j] = vol*( mu_eff*delta_ij*(g_a . g_b)
    //                    + cgeo * h_a[j]*h_b[i] + lam * h_a[i]*h_b[j] )
    float o[36];
#pragma unroll
    for (int a = 0; a < 3; a++) {
#pragma unroll
        for (int b = 0; b < 3; b++) {
            float gg = ga[a][0] * ga[b][0] + ga[a][1] * ga[b][1];
#pragma unroll
            for (int i = 0; i < 2; i++) {
#pragma unroll
                for (int j = 0; j < 2; j++) {
                    float v = cgeo * h[a][j] * h[b][i] + lam * h[a][i] * h[b][j];
                    if (i == j) v += mu_eff * gg;
                    o[((a * 2 + i) * 3 + b) * 2 + j] = v * vol;
                }
            }
        }
    }

    // stage element-contiguous (stride 36 floats), 9x STS.128 conflict-free
    {
        float4* row = reinterpret_cast<float4*>(smem + tid * 36);
#pragma unroll
        for (int k = 0; k < 9; k++)
            row[k] = make_float4(o[4 * k + 0], o[4 * k + 1], o[4 * k + 2], o[4 * k + 3]);
    }

    __syncthreads();

    // linear copy-out: 2304 float4 per block, LDS.128 + STG.128, fully coalesced
    {
        const float4* s4 = reinterpret_cast<const float4*>(smem);
        float4* o4 = reinterpret_cast<float4*>(out) + (size_t)blk * (TPB * 9);
#pragma unroll
        for (int it = 0; it < 9; it++)
            o4[it * TPB + tid] = s4[it * TPB + tid];
    }
}

extern "C" void kernel_launch(void* const* d_in, const int* in_sizes, int n_in,
                              void* d_out, int out_size) {
    // metadata order: U, coords, state, conns, shapes, shapeGrads, vols, blocks0, blocks1
    const float* U      = (const float*)d_in[0];
    // d_in[1] = coords  (unused by the energy)
    const float* state  = (const float*)d_in[2];
    const int*   conns  = (const int*)  d_in[3];
    // d_in[4] = shapes  (unused by the energy)
    const float* sg     = (const float*)d_in[5];
    const float* vols   = (const float*)d_in[6];
    // d_in[7] = blocks0 (implied 0 by the memset)
    const int*   b1     = (const int*)  d_in[8];
    float* out = (float*)d_out;

    void* matid_ptr = nullptr;
    cudaGetSymbolAddress(&matid_ptr, g_matid);
    cudaMemsetAsync(matid_ptr, 0, E_TOT);

    mark_b1_kernel<<<(HALF_E / 4 + TPB - 1) / TPB, TPB>>>(b1);

    hess_kernel<<<E_TOT / TPB, TPB>>>(U, state, conns, sg, vols, out);
}